// round 15
// baseline (speedup 1.0000x reference)
#include <cuda_runtime.h>
#include <cuda_fp16.h>
#include <cstdint>

#define D    128
#define LDH  136                // half row stride in smem (8-half pad, conflict-free ldmatrix)
#define TILE_B (128 * LDH * 2)  // 34816 bytes per staged 128x128 fp16 tile
#define TL   (128 * LDH)

// fp16 scratch tables (allocation-free __device__ globals)
__device__ __half g_Ktab[50000 * D];   // tanh((attr + item) @ Wk^T + bk)
__device__ __half g_A   [50000 * D];   // item @ Wv^T
__device__ __half g_B   [ 5000 * D];   // opin @ Wv^T + bv
__device__ __half g_Q   [10000 * D];   // tanh(user @ Wq^T + bq)

static __device__ __forceinline__ uint32_t smem_u32(const void* p) {
    return (uint32_t)__cvta_generic_to_shared(p);
}
static __device__ __forceinline__ void ldsm_x4(uint32_t& r0, uint32_t& r1,
                                               uint32_t& r2, uint32_t& r3, uint32_t addr) {
    asm volatile("ldmatrix.sync.aligned.m8n8.x4.shared.b16 {%0,%1,%2,%3}, [%4];"
                 : "=r"(r0), "=r"(r1), "=r"(r2), "=r"(r3) : "r"(addr));
}
static __device__ __forceinline__ void mma16816(float* d,
                                                const uint32_t* a, const uint32_t* b) {
    asm volatile("mma.sync.aligned.m16n8k16.row.col.f32.f16.f16.f32 "
                 "{%0,%1,%2,%3}, {%4,%5,%6,%7}, {%8,%9}, {%0,%1,%2,%3};"
                 : "+f"(d[0]), "+f"(d[1]), "+f"(d[2]), "+f"(d[3])
                 : "r"(a[0]), "r"(a[1]), "r"(a[2]), "r"(a[3]), "r"(b[0]), "r"(b[1]));
}
static __device__ __forceinline__ float tanha(float x) {
    float y;
    asm("tanh.approx.f32 %0, %1;" : "=f"(y) : "f"(x));
    return y;
}
static __device__ __forceinline__ __half2 tanh2(__half2 x) {
    uint32_t xi = *(uint32_t*)&x, yi;
    asm("tanh.approx.f16x2 %0, %1;" : "=r"(yi) : "r"(xi));
    return *(__half2*)&yi;
}

// Stage a 128x128 fp32 tile as fp16 (hi only), optional fp32 pre-add vector.
static __device__ __forceinline__ void stage_x(__half* hi,
    const float* __restrict__ src, const float* __restrict__ pre,
    int row0, int M, int tid)
{
    #pragma unroll
    for (int idx = tid; idx < 128 * 32; idx += 512) {
        int r  = idx >> 5;
        int c4 = (idx & 31) << 2;
        int gr = row0 + r;
        float4 v = make_float4(0.f, 0.f, 0.f, 0.f);
        if (gr < M) v = *(const float4*)(src + (size_t)gr * D + c4);
        if (pre) {
            float4 a = __ldg((const float4*)(pre + c4));
            v.x += a.x; v.y += a.y; v.z += a.z; v.w += a.w;
        }
        __half2 ph0 = __floats2half2_rn(v.x, v.y);
        __half2 ph1 = __floats2half2_rn(v.z, v.w);
        uint2 uh;
        uh.x = *(uint32_t*)&ph0; uh.y = *(uint32_t*)&ph1;
        *(uint2*)(hi + r * LDH + c4) = uh;
    }
}

// Convert a 128x128 fp32 W tile to hi/lo fp16 padded smem (512 threads).
static __device__ __forceinline__ void stage_w_conv(__half* hi, __half* lo,
    const float* __restrict__ W, int tid)
{
    #pragma unroll
    for (int idx = tid; idx < 128 * 32; idx += 512) {
        int r  = idx >> 5;
        int c4 = (idx & 31) << 2;
        float4 v = __ldg((const float4*)(W + (size_t)r * D + c4));
        __half h0 = __float2half_rn(v.x), h1 = __float2half_rn(v.y);
        __half h2 = __float2half_rn(v.z), h3 = __float2half_rn(v.w);
        __half l0 = __float2half_rn(v.x - __half2float(h0));
        __half l1 = __float2half_rn(v.y - __half2float(h1));
        __half l2 = __float2half_rn(v.z - __half2float(h2));
        __half l3 = __float2half_rn(v.w - __half2float(h3));
        __half2 ph0 = __halves2half2(h0, h1), ph1 = __halves2half2(h2, h3);
        __half2 pl0 = __halves2half2(l0, l1), pl1 = __halves2half2(l2, l3);
        uint2 uh, ul;
        uh.x = *(uint32_t*)&ph0; uh.y = *(uint32_t*)&ph1;
        ul.x = *(uint32_t*)&pl0; ul.y = *(uint32_t*)&pl1;
        *(uint2*)(hi + r * LDH + c4) = uh;
        *(uint2*)(lo + r * LDH + c4) = ul;
    }
}

// One output per CTA (uniform role), 256 rows per CTA (two 128-row sub-tiles).
// W converted fp32 -> hi/lo fp16 inline. 2-pass: Xhi*(Whi + Wlo) = Xhi*W.
// smem = 3 tiles -> 2 CTAs/SM.
__global__ void __launch_bounds__(512, 2) tab_gemm_all(
    const float* __restrict__ item_table, const float* __restrict__ opin_table,
    const float* __restrict__ user_emb,   const float* __restrict__ attr,
    const float* __restrict__ Wq, const float* __restrict__ bq,
    const float* __restrict__ Wk, const float* __restrict__ bk,
    const float* __restrict__ Wv, const float* __restrict__ bv,
    __half* __restrict__ pK, __half* __restrict__ pA,
    __half* __restrict__ pB, __half* __restrict__ pQ,
    int n_item, int n_opi, int n_user, int nbK, int nbA, int nbB)
{
    extern __shared__ char smc[];
    __half* Xhi = (__half*)smc;
    __half* Whi = Xhi + TL;
    __half* Wlo = Whi + TL;

    const int tid  = threadIdx.x;
    const int lane = tid & 31;
    const int wid  = tid >> 5;
    const int wm   = wid >> 2;
    const int wn   = wid & 3;

    // uniform role selection
    const int bid = blockIdx.x;
    const float *X, *Wp, *biasp, *pre;
    __half* outp;
    int M, rbase;
    bool dotanh;
    if (bid < nbK) {            // Ktab = tanh((item + attr) @ Wk^T + bk)
        X = item_table; Wp = Wk; biasp = bk; pre = attr;
        outp = pK; M = n_item; rbase = bid * 256; dotanh = true;
    } else if (bid < nbK + nbA) {   // A = item @ Wv^T
        X = item_table; Wp = Wv; biasp = nullptr; pre = nullptr;
        outp = pA; M = n_item; rbase = (bid - nbK) * 256; dotanh = false;
    } else if (bid < nbK + nbA + nbB) {  // B = opin @ Wv^T + bv
        X = opin_table; Wp = Wv; biasp = bv; pre = nullptr;
        outp = pB; M = n_opi; rbase = (bid - nbK - nbA) * 256; dotanh = false;
    } else {                    // Q = tanh(user @ Wq^T + bq)
        X = user_emb; Wp = Wq; biasp = bq; pre = nullptr;
        outp = pQ; M = n_user; rbase = (bid - nbK - nbA - nbB) * 256; dotanh = true;
    }

    // Prologue: convert W inline + stage X sub-0
    stage_w_conv(Whi, Wlo, Wp, tid);
    stage_x(Xhi, X, pre, rbase, M, tid);

    // ldmatrix lane-address mapping
    const int ag   = lane >> 3;
    const int arow = wm * 32 + (ag & 1) * 8 + (lane & 7);
    const int acol = (ag >> 1) * 8;
    const uint32_t aHi = smem_u32(Xhi + arow * LDH + acol);
    const int brow = wn * 32 + (ag >> 1) * 8 + (lane & 7);
    const int bcol = (ag & 1) * 8;
    const uint32_t bHi = smem_u32(Whi + brow * LDH + bcol);
    const uint32_t bLo = smem_u32(Wlo + brow * LDH + bcol);

    __syncthreads();   // X sub-0 + W tiles staged

    #pragma unroll 1
    for (int sub = 0; sub < 2; sub++) {
        const int row0 = rbase + sub * 128;
        if (row0 >= M) break;

        if (sub > 0) {
            stage_x(Xhi, X, pre, row0, M, tid);
            __syncthreads();
        }

        float acc[2][4][4];   // [mf][nf][c]
        #pragma unroll
        for (int mf = 0; mf < 2; mf++)
            #pragma unroll
            for (int nf = 0; nf < 4; nf++)
                #pragma unroll
                for (int c = 0; c < 4; c++) acc[mf][nf][c] = 0.f;

        #pragma unroll
        for (int ks = 0; ks < 8; ks++) {
            const uint32_t ko = (uint32_t)ks * 32;
            uint32_t ahi[2][4];
            #pragma unroll
            for (int mf = 0; mf < 2; mf++) {
                const uint32_t mo = (uint32_t)(mf * 16 * LDH) * 2;
                ldsm_x4(ahi[mf][0], ahi[mf][1], ahi[mf][2], ahi[mf][3], aHi + mo + ko);
            }
            #pragma unroll
            for (int nh = 0; nh < 2; nh++) {
                const uint32_t no = (uint32_t)(nh * 16 * LDH) * 2;
                uint32_t bh[4];
                ldsm_x4(bh[0], bh[1], bh[2], bh[3], bHi + no + ko);
                mma16816(acc[0][nh*2],     ahi[0], bh + 0);
                mma16816(acc[1][nh*2],     ahi[1], bh + 0);
                mma16816(acc[0][nh*2 + 1], ahi[0], bh + 2);
                mma16816(acc[1][nh*2 + 1], ahi[1], bh + 2);
                uint32_t bl[4];
                ldsm_x4(bl[0], bl[1], bl[2], bl[3], bLo + no + ko);
                mma16816(acc[0][nh*2],     ahi[0], bl + 0);
                mma16816(acc[1][nh*2],     ahi[1], bl + 0);
                mma16816(acc[0][nh*2 + 1], ahi[0], bl + 2);
                mma16816(acc[1][nh*2 + 1], ahi[1], bl + 2);
            }
        }
        __syncthreads();   // all ldsm done; Xhi free for next sub-tile

        // epilogue: bias read directly from fp32 vector (L2-hit), then tanh
        #pragma unroll
        for (int mf = 0; mf < 2; mf++) {
            const int r0 = row0 + wm * 32 + mf * 16 + (lane >> 2);
            const int r1 = r0 + 8;
            #pragma unroll
            for (int nf = 0; nf < 4; nf++) {
                const int col = wn * 32 + nf * 8 + 2 * (lane & 3);
                float e0 = biasp ? __ldg(biasp + col)     : 0.f;
                float e1 = biasp ? __ldg(biasp + col + 1) : 0.f;
                float v0 = acc[mf][nf][0] + e0, v1 = acc[mf][nf][1] + e1;
                float v2 = acc[mf][nf][2] + e0, v3 = acc[mf][nf][3] + e1;
                if (dotanh) { v0 = tanha(v0); v1 = tanha(v1); v2 = tanha(v2); v3 = tanha(v3); }
                if (r0 < M) *(__half2*)(outp + (size_t)r0 * D + col) = __floats2half2_rn(v0, v1);
                if (r1 < M) *(__half2*)(outp + (size_t)r1 * D + col) = __floats2half2_rn(v2, v3);
            }
        }
    }
}

// TWO warps per user (split step range), smem combine. 256 thr = 8 warps = 4 users.
__global__ void __launch_bounds__(256) attend_kernel(
    const int* __restrict__ item_seqs,
    const int* __restrict__ opin_seqs,
    float* __restrict__ out, int U, int L)
{
    __shared__ float part[4][128];

    const int tid   = threadIdx.x;
    const int lane  = tid & 31;
    const int wid   = tid >> 5;
    const int uslot = wid >> 1;          // 0..3 user slot in block
    const int half  = wid & 1;           // which half of the sequence
    const int gw    = blockIdx.x * 4 + uslot;
    const bool live = (gw < U);

    const uint2* Kt = (const uint2*)g_Ktab;   // 32 uint2 per row
    const uint2* At = (const uint2*)g_A;
    const uint2* Bt = (const uint2*)g_B;

    float4 acc = make_float4(0.f, 0.f, 0.f, 0.f);

    if (live) {
        uint2 qw = *((const uint2*)g_Q + (size_t)gw * 32 + lane);
        float2 q01 = __half22float2(*reinterpret_cast<__half2*>(&qw.x));
        float2 q23 = __half22float2(*reinterpret_cast<__half2*>(&qw.y));

        const int* is = item_seqs + (size_t)gw * L;
        const int* os = opin_seqs + (size_t)gw * L;

        const int lmid = (L / 2) & ~3;                    // 24 for L=50 (8B-aligned split)
        const int l0 = half ? lmid : 0;
        const int l1 = half ? L    : lmid;
        const int lv = l0 + ((l1 - l0) & ~3);             // vectorized end

        for (int l = l0; l < lv; l += 4) {
            int2 i01 = __ldg((const int2*)(is + l));
            int2 i23 = __ldg((const int2*)(is + l + 2));
            int2 o01 = __ldg((const int2*)(os + l));
            int2 o23 = __ldg((const int2*)(os + l + 2));
            int ii[4] = {i01.x, i01.y, i23.x, i23.y};
            int oo[4] = {o01.x, o01.y, o23.x, o23.y};

            uint2 kw[4], aw[4], bw[4];
            #pragma unroll
            for (int t = 0; t < 4; t++) {
                kw[t] = __ldg(Kt + (size_t)ii[t] * 32 + lane);
                aw[t] = __ldg(At + (size_t)ii[t] * 32 + lane);
                bw[t] = __ldg(Bt + (size_t)oo[t] * 32 + lane);
            }

            float w[4];
            #pragma unroll
            for (int t = 0; t < 4; t++) {
                float2 k01 = __half22float2(*reinterpret_cast<__half2*>(&kw[t].x));
                float2 k23 = __half22float2(*reinterpret_cast<__half2*>(&kw[t].y));
                w[t] = q01.x * k01.x + q01.y * k01.y + q23.x * k23.x + q23.y * k23.y;
            }
            #pragma unroll
            for (int s = 16; s; s >>= 1) {
                w[0] += __shfl_xor_sync(0xffffffffu, w[0], s);
                w[1] += __shfl_xor_sync(0xffffffffu, w[1], s);
                w[2] += __shfl_xor_sync(0xffffffffu, w[2], s);
                w[3] += __shfl_xor_sync(0xffffffffu, w[3], s);
            }
            #pragma unroll
            for (int t = 0; t < 4; t++) {
                float wt = (ii[t] > 0) ? w[t] : 0.f;
                __half2 sx = tanh2(__hadd2(*reinterpret_cast<__half2*>(&aw[t].x),
                                           *reinterpret_cast<__half2*>(&bw[t].x)));
                __half2 sy = tanh2(__hadd2(*reinterpret_cast<__half2*>(&aw[t].y),
                                           *reinterpret_cast<__half2*>(&bw[t].y)));
                float2 fx = __half22float2(sx), fy = __half22float2(sy);
                acc.x += wt * fx.x;
                acc.y += wt * fx.y;
                acc.z += wt * fy.x;
                acc.w += wt * fy.y;
            }
        }
        for (int l = lv; l < l1; ++l) {
            int i = __ldg(is + l);
            int o = __ldg(os + l);
            uint2 kw = __ldg(Kt + (size_t)i * 32 + lane);
            uint2 aw = __ldg(At + (size_t)i * 32 + lane);
            uint2 bw = __ldg(Bt + (size_t)o * 32 + lane);
            float2 k01 = __half22float2(*reinterpret_cast<__half2*>(&kw.x));
            float2 k23 = __half22float2(*reinterpret_cast<__half2*>(&kw.y));
            float w = q01.x * k01.x + q01.y * k01.y + q23.x * k23.x + q23.y * k23.y;
            #pragma unroll
            for (int s = 16; s; s >>= 1) w += __shfl_xor_sync(0xffffffffu, w, s);
            w = (i > 0) ? w : 0.f;
            __half2 sx = tanh2(__hadd2(*reinterpret_cast<__half2*>(&aw.x),
                                       *reinterpret_cast<__half2*>(&bw.x)));
            __half2 sy = tanh2(__hadd2(*reinterpret_cast<__half2*>(&aw.y),
                                       *reinterpret_cast<__half2*>(&bw.y)));
            float2 fx = __half22float2(sx), fy = __half22float2(sy);
            acc.x += w * fx.x;
            acc.y += w * fx.y;
            acc.z += w * fy.x;
            acc.w += w * fy.y;
        }
    }

    // combine halves: half1 stores partial; half0 adds and writes out
    if (live && half == 1)
        *(float4*)(&part[uslot][lane * 4]) = acc;
    __syncthreads();
    if (live && half == 0) {
        float4 p = *(const float4*)(&part[uslot][lane * 4]);
        acc.x += p.x; acc.y += p.y; acc.z += p.z; acc.w += p.w;
        *(float4*)(out + (size_t)gw * D + lane * 4) = acc;
    }
}

extern "C" void kernel_launch(void* const* d_in, const int* in_sizes, int n_in,
                              void* d_out, int out_size)
{
    const float* item_table = (const float*)d_in[0];
    const float* opin_table = (const float*)d_in[1];
    const float* user_emb   = (const float*)d_in[2];
    const float* attr       = (const float*)d_in[3];
    const float* Wq         = (const float*)d_in[4];
    const float* bq         = (const float*)d_in[5];
    const float* Wk         = (const float*)d_in[6];
    const float* bk         = (const float*)d_in[7];
    const float* Wv         = (const float*)d_in[8];
    const float* bv         = (const float*)d_in[9];
    const int*   item_seqs  = (const int*)d_in[10];
    const int*   opin_seqs  = (const int*)d_in[11];
    float*       out        = (float*)d_out;

    const int n_item = in_sizes[0] / D;
    const int n_opi  = in_sizes[1] / D;
    const int U      = in_sizes[2] / D;
    const int L      = in_sizes[10] / U;

    __half *pK, *pA, *pB, *pQ;
    cudaGetSymbolAddress((void**)&pK, g_Ktab);
    cudaGetSymbolAddress((void**)&pA, g_A);
    cudaGetSymbolAddress((void**)&pB, g_B);
    cudaGetSymbolAddress((void**)&pQ, g_Q);

    const int nbK = (n_item + 255) / 256;
    const int nbA = nbK;
    const int nbB = (n_opi + 255) / 256;
    const int nbQ = (U + 255) / 256;

    const int smemB = 3 * TILE_B;   // 104448 B -> 2 CTAs/SM
    cudaFuncSetAttribute((const void*)tab_gemm_all,
                         cudaFuncAttributeMaxDynamicSharedMemorySize, smemB);

    tab_gemm_all<<<nbK + nbA + nbB + nbQ, 512, smemB>>>(
        item_table, opin_table, user_emb, attr,
        Wq, bq, Wk, bk, Wv, bv,
        pK, pA, pB, pQ, n_item, n_opi, U, nbK, nbA, nbB);

    const int blocks = (U + 3) / 4;   // 4 users per 256-thread block, 2 warps/user
    attend_kernel<<<blocks, 256>>>(item_seqs, opin_seqs, out, U, L);
}

// round 17
// speedup vs baseline: 1.0639x; 1.0639x over previous
#include <cuda_runtime.h>
#include <cuda_fp16.h>
#include <cstdint>

#define D    128
#define LDH  136                // half row stride in smem (8-half pad, conflict-free ldmatrix)
#define TILE_B (128 * LDH * 2)  // 34816 bytes per staged 128x128 fp16 tile
#define TL   (128 * LDH)

// fp16 scratch tables (allocation-free __device__ globals)
// g_KA: interleaved K/A rows of 256 halves — per 8-half group g:
//   [g*8 .. g*8+3] = Ktab cols [g*4 .. g*4+3], [g*8+4 .. g*8+7] = A cols [g*4 .. g*4+3]
__device__ __half g_KA[50000 * 256];
__device__ __half g_B [ 5000 * D];     // opin @ Wv^T + bv
__device__ __half g_Q [10000 * D];     // tanh(user @ Wq^T + bq)

static __device__ __forceinline__ uint32_t smem_u32(const void* p) {
    return (uint32_t)__cvta_generic_to_shared(p);
}
static __device__ __forceinline__ void ldsm_x4(uint32_t& r0, uint32_t& r1,
                                               uint32_t& r2, uint32_t& r3, uint32_t addr) {
    asm volatile("ldmatrix.sync.aligned.m8n8.x4.shared.b16 {%0,%1,%2,%3}, [%4];"
                 : "=r"(r0), "=r"(r1), "=r"(r2), "=r"(r3) : "r"(addr));
}
static __device__ __forceinline__ void mma16816(float* d,
                                                const uint32_t* a, const uint32_t* b) {
    asm volatile("mma.sync.aligned.m16n8k16.row.col.f32.f16.f16.f32 "
                 "{%0,%1,%2,%3}, {%4,%5,%6,%7}, {%8,%9}, {%0,%1,%2,%3};"
                 : "+f"(d[0]), "+f"(d[1]), "+f"(d[2]), "+f"(d[3])
                 : "r"(a[0]), "r"(a[1]), "r"(a[2]), "r"(a[3]), "r"(b[0]), "r"(b[1]));
}
static __device__ __forceinline__ float tanha(float x) {
    float y;
    asm("tanh.approx.f32 %0, %1;" : "=f"(y) : "f"(x));
    return y;
}
static __device__ __forceinline__ __half2 tanh2(__half2 x) {
    uint32_t xi = *(uint32_t*)&x, yi;
    asm("tanh.approx.f16x2 %0, %1;" : "=r"(yi) : "r"(xi));
    return *(__half2*)&yi;
}

// Stage a 128x128 fp32 tile as fp16 (hi only), optional fp32 pre-add vector.
static __device__ __forceinline__ void stage_x(__half* hi,
    const float* __restrict__ src, const float* __restrict__ pre,
    int row0, int M, int tid)
{
    #pragma unroll
    for (int idx = tid; idx < 128 * 32; idx += 512) {
        int r  = idx >> 5;
        int c4 = (idx & 31) << 2;
        int gr = row0 + r;
        float4 v = make_float4(0.f, 0.f, 0.f, 0.f);
        if (gr < M) v = *(const float4*)(src + (size_t)gr * D + c4);
        if (pre) {
            float4 a = __ldg((const float4*)(pre + c4));
            v.x += a.x; v.y += a.y; v.z += a.z; v.w += a.w;
        }
        __half2 ph0 = __floats2half2_rn(v.x, v.y);
        __half2 ph1 = __floats2half2_rn(v.z, v.w);
        uint2 uh;
        uh.x = *(uint32_t*)&ph0; uh.y = *(uint32_t*)&ph1;
        *(uint2*)(hi + r * LDH + c4) = uh;
    }
}

// Convert a 128x128 fp32 W tile to hi/lo fp16 padded smem (512 threads).
static __device__ __forceinline__ void stage_w_conv(__half* hi, __half* lo,
    const float* __restrict__ W, int tid)
{
    #pragma unroll
    for (int idx = tid; idx < 128 * 32; idx += 512) {
        int r  = idx >> 5;
        int c4 = (idx & 31) << 2;
        float4 v = __ldg((const float4*)(W + (size_t)r * D + c4));
        __half h0 = __float2half_rn(v.x), h1 = __float2half_rn(v.y);
        __half h2 = __float2half_rn(v.z), h3 = __float2half_rn(v.w);
        __half l0 = __float2half_rn(v.x - __half2float(h0));
        __half l1 = __float2half_rn(v.y - __half2float(h1));
        __half l2 = __float2half_rn(v.z - __half2float(h2));
        __half l3 = __float2half_rn(v.w - __half2float(h3));
        __half2 ph0 = __halves2half2(h0, h1), ph1 = __halves2half2(h2, h3);
        __half2 pl0 = __halves2half2(l0, l1), pl1 = __halves2half2(l2, l3);
        uint2 uh, ul;
        uh.x = *(uint32_t*)&ph0; uh.y = *(uint32_t*)&ph1;
        ul.x = *(uint32_t*)&pl0; ul.y = *(uint32_t*)&pl1;
        *(uint2*)(hi + r * LDH + c4) = uh;
        *(uint2*)(lo + r * LDH + c4) = ul;
    }
}

// One output per CTA, 256 rows per CTA (two 128-row sub-tiles).
// W converted fp32 -> hi/lo fp16 inline. 2-pass: Xhi*(Whi + Wlo) = Xhi*W.
// K/A roles write to the interleaved g_KA layout (sel 0 / 4, row stride 256).
__global__ void __launch_bounds__(512, 2) tab_gemm_all(
    const float* __restrict__ item_table, const float* __restrict__ opin_table,
    const float* __restrict__ user_emb,   const float* __restrict__ attr,
    const float* __restrict__ Wq, const float* __restrict__ bq,
    const float* __restrict__ Wk, const float* __restrict__ bk,
    const float* __restrict__ Wv, const float* __restrict__ bv,
    __half* __restrict__ pKA, __half* __restrict__ pB, __half* __restrict__ pQ,
    int n_item, int n_opi, int n_user, int nbK, int nbA, int nbB)
{
    extern __shared__ char smc[];
    __half* Xhi = (__half*)smc;
    __half* Whi = Xhi + TL;
    __half* Wlo = Whi + TL;

    const int tid  = threadIdx.x;
    const int lane = tid & 31;
    const int wid  = tid >> 5;
    const int wm   = wid >> 2;
    const int wn   = wid & 3;

    // role selection
    const int bid = blockIdx.x;
    const float *X, *Wp, *biasp, *pre;
    __half* outp;
    int M, rbase, sel = 0, ostride;
    bool dotanh, inter;
    if (bid < nbK) {            // Ktab = tanh((item + attr) @ Wk^T + bk) -> g_KA sel 0
        X = item_table; Wp = Wk; biasp = bk; pre = attr;
        outp = pKA; M = n_item; rbase = bid * 256; dotanh = true;
        inter = true; sel = 0; ostride = 256;
    } else if (bid < nbK + nbA) {   // A = item @ Wv^T -> g_KA sel 4
        X = item_table; Wp = Wv; biasp = nullptr; pre = nullptr;
        outp = pKA; M = n_item; rbase = (bid - nbK) * 256; dotanh = false;
        inter = true; sel = 4; ostride = 256;
    } else if (bid < nbK + nbA + nbB) {  // B = opin @ Wv^T + bv
        X = opin_table; Wp = Wv; biasp = bv; pre = nullptr;
        outp = pB; M = n_opi; rbase = (bid - nbK - nbA) * 256; dotanh = false;
        inter = false; ostride = 128;
    } else {                    // Q = tanh(user @ Wq^T + bq)
        X = user_emb; Wp = Wq; biasp = bq; pre = nullptr;
        outp = pQ; M = n_user; rbase = (bid - nbK - nbA - nbB) * 256; dotanh = true;
        inter = false; ostride = 128;
    }

    // Prologue: convert W inline + stage X sub-0
    stage_w_conv(Whi, Wlo, Wp, tid);
    stage_x(Xhi, X, pre, rbase, M, tid);

    // ldmatrix lane-address mapping
    const int ag   = lane >> 3;
    const int arow = wm * 32 + (ag & 1) * 8 + (lane & 7);
    const int acol = (ag >> 1) * 8;
    const uint32_t aHi = smem_u32(Xhi + arow * LDH + acol);
    const int brow = wn * 32 + (ag >> 1) * 8 + (lane & 7);
    const int bcol = (ag & 1) * 8;
    const uint32_t bHi = smem_u32(Whi + brow * LDH + bcol);
    const uint32_t bLo = smem_u32(Wlo + brow * LDH + bcol);

    __syncthreads();   // X sub-0 + W tiles staged

    #pragma unroll 1
    for (int sub = 0; sub < 2; sub++) {
        const int row0 = rbase + sub * 128;
        if (row0 >= M) break;

        if (sub > 0) {
            stage_x(Xhi, X, pre, row0, M, tid);
            __syncthreads();
        }

        float acc[2][4][4];   // [mf][nf][c]
        #pragma unroll
        for (int mf = 0; mf < 2; mf++)
            #pragma unroll
            for (int nf = 0; nf < 4; nf++)
                #pragma unroll
                for (int c = 0; c < 4; c++) acc[mf][nf][c] = 0.f;

        #pragma unroll
        for (int ks = 0; ks < 8; ks++) {
            const uint32_t ko = (uint32_t)ks * 32;
            uint32_t ahi[2][4];
            #pragma unroll
            for (int mf = 0; mf < 2; mf++) {
                const uint32_t mo = (uint32_t)(mf * 16 * LDH) * 2;
                ldsm_x4(ahi[mf][0], ahi[mf][1], ahi[mf][2], ahi[mf][3], aHi + mo + ko);
            }
            #pragma unroll
            for (int nh = 0; nh < 2; nh++) {
                const uint32_t no = (uint32_t)(nh * 16 * LDH) * 2;
                uint32_t bh[4];
                ldsm_x4(bh[0], bh[1], bh[2], bh[3], bHi + no + ko);
                mma16816(acc[0][nh*2],     ahi[0], bh + 0);
                mma16816(acc[1][nh*2],     ahi[1], bh + 0);
                mma16816(acc[0][nh*2 + 1], ahi[0], bh + 2);
                mma16816(acc[1][nh*2 + 1], ahi[1], bh + 2);
                uint32_t bl[4];
                ldsm_x4(bl[0], bl[1], bl[2], bl[3], bLo + no + ko);
                mma16816(acc[0][nh*2],     ahi[0], bl + 0);
                mma16816(acc[1][nh*2],     ahi[1], bl + 0);
                mma16816(acc[0][nh*2 + 1], ahi[0], bl + 2);
                mma16816(acc[1][nh*2 + 1], ahi[1], bl + 2);
            }
        }
        __syncthreads();   // all ldsm done; Xhi free for next sub-tile

        // epilogue: bias from fp32 vector (L2-hit), tanh, interleave-aware store
        #pragma unroll
        for (int mf = 0; mf < 2; mf++) {
            const int r0 = row0 + wm * 32 + mf * 16 + (lane >> 2);
            const int r1 = r0 + 8;
            #pragma unroll
            for (int nf = 0; nf < 4; nf++) {
                const int col = wn * 32 + nf * 8 + 2 * (lane & 3);
                float e0 = biasp ? __ldg(biasp + col)     : 0.f;
                float e1 = biasp ? __ldg(biasp + col + 1) : 0.f;
                float v0 = acc[mf][nf][0] + e0, v1 = acc[mf][nf][1] + e1;
                float v2 = acc[mf][nf][2] + e0, v3 = acc[mf][nf][3] + e1;
                if (dotanh) { v0 = tanha(v0); v1 = tanha(v1); v2 = tanha(v2); v3 = tanha(v3); }
                const int ocol = inter ? (((col >> 2) << 3) + sel + (col & 3)) : col;
                if (r0 < M) *(__half2*)(outp + (size_t)r0 * ostride + ocol) = __floats2half2_rn(v0, v1);
                if (r1 < M) *(__half2*)(outp + (size_t)r1 * ostride + ocol) = __floats2half2_rn(v2, v3);
            }
        }
    }
}

// One warp per user; 4-step pipelined; fused K/A gather (one uint4 per step/lane).
// g_KA row = 256 halves = 32 uint4 (stride fixed from R16's OOB bug).
__global__ void __launch_bounds__(256) attend_kernel(
    const int* __restrict__ item_seqs,
    const int* __restrict__ opin_seqs,
    float* __restrict__ out, int U, int L)
{
    const int gw   = (int)((blockIdx.x * blockDim.x + threadIdx.x) >> 5);
    const int lane = threadIdx.x & 31;
    if (gw >= U) return;

    const uint4* KAt = (const uint4*)g_KA;   // 32 uint4 per row (256 halves)
    const uint2* Bt  = (const uint2*)g_B;    // 32 uint2 per row

    uint2 qw = *((const uint2*)g_Q + (size_t)gw * 32 + lane);
    float2 q01 = __half22float2(*reinterpret_cast<__half2*>(&qw.x));
    float2 q23 = __half22float2(*reinterpret_cast<__half2*>(&qw.y));

    float4 acc = make_float4(0.f, 0.f, 0.f, 0.f);
    const int* is = item_seqs + (size_t)gw * L;
    const int* os = opin_seqs + (size_t)gw * L;

    const int Lm = L & ~3;
    for (int l = 0; l < Lm; l += 4) {
        int2 i01 = __ldg((const int2*)(is + l));
        int2 i23 = __ldg((const int2*)(is + l + 2));
        int2 o01 = __ldg((const int2*)(os + l));
        int2 o23 = __ldg((const int2*)(os + l + 2));
        int ii[4] = {i01.x, i01.y, i23.x, i23.y};
        int oo[4] = {o01.x, o01.y, o23.x, o23.y};

        uint4 ka[4];
        uint2 bw[4];
        #pragma unroll
        for (int t = 0; t < 4; t++) {
            ka[t] = __ldg(KAt + (size_t)ii[t] * 32 + lane);
            bw[t] = __ldg(Bt + (size_t)oo[t] * 32 + lane);
        }

        float w[4];
        #pragma unroll
        for (int t = 0; t < 4; t++) {
            float2 k01 = __half22float2(*reinterpret_cast<__half2*>(&ka[t].x));
            float2 k23 = __half22float2(*reinterpret_cast<__half2*>(&ka[t].y));
            w[t] = q01.x * k01.x + q01.y * k01.y + q23.x * k23.x + q23.y * k23.y;
        }
        #pragma unroll
        for (int s = 16; s; s >>= 1) {
            w[0] += __shfl_xor_sync(0xffffffffu, w[0], s);
            w[1] += __shfl_xor_sync(0xffffffffu, w[1], s);
            w[2] += __shfl_xor_sync(0xffffffffu, w[2], s);
            w[3] += __shfl_xor_sync(0xffffffffu, w[3], s);
        }
        #pragma unroll
        for (int t = 0; t < 4; t++) {
            float wt = (ii[t] > 0) ? w[t] : 0.f;
            __half2 sx = tanh2(__hadd2(*reinterpret_cast<__half2*>(&ka[t].z),
                                       *reinterpret_cast<__half2*>(&bw[t].x)));
            __half2 sy = tanh2(__hadd2(*reinterpret_cast<__half2*>(&ka[t].w),
                                       *reinterpret_cast<__half2*>(&bw[t].y)));
            float2 fx = __half22float2(sx), fy = __half22float2(sy);
            acc.x += wt * fx.x;
            acc.y += wt * fx.y;
            acc.z += wt * fy.x;
            acc.w += wt * fy.y;
        }
    }
    for (int l = Lm; l < L; ++l) {
        int i = __ldg(is + l);
        int o = __ldg(os + l);
        uint4 ka = __ldg(KAt + (size_t)i * 32 + lane);
        uint2 bw = __ldg(Bt + (size_t)o * 32 + lane);
        float2 k01 = __half22float2(*reinterpret_cast<__half2*>(&ka.x));
        float2 k23 = __half22float2(*reinterpret_cast<__half2*>(&ka.y));
        float w = q01.x * k01.x + q01.y * k01.y + q23.x * k23.x + q23.y * k23.y;
        #pragma unroll
        for (int s = 16; s; s >>= 1) w += __shfl_xor_sync(0xffffffffu, w, s);
        w = (i > 0) ? w : 0.f;
        __half2 sx = tanh2(__hadd2(*reinterpret_cast<__half2*>(&ka.z),
                                   *reinterpret_cast<__half2*>(&bw.x)));
        __half2 sy = tanh2(__hadd2(*reinterpret_cast<__half2*>(&ka.w),
                                   *reinterpret_cast<__half2*>(&bw.y)));
        float2 fx = __half22float2(sx), fy = __half22float2(sy);
        acc.x += w * fx.x;
        acc.y += w * fx.y;
        acc.z += w * fy.x;
        acc.w += w * fy.y;
    }
    *(float4*)(out + (size_t)gw * D + lane * 4) = acc;
}

extern "C" void kernel_launch(void* const* d_in, const int* in_sizes, int n_in,
                              void* d_out, int out_size)
{
    const float* item_table = (const float*)d_in[0];
    const float* opin_table = (const float*)d_in[1];
    const float* user_emb   = (const float*)d_in[2];
    const float* attr       = (const float*)d_in[3];
    const float* Wq         = (const float*)d_in[4];
    const float* bq         = (const float*)d_in[5];
    const float* Wk         = (const float*)d_in[6];
    const float* bk         = (const float*)d_in[7];
    const float* Wv         = (const float*)d_in[8];
    const float* bv         = (const float*)d_in[9];
    const int*   item_seqs  = (const int*)d_in[10];
    const int*   opin_seqs  = (const int*)d_in[11];
    float*       out        = (float*)d_out;

    const int n_item = in_sizes[0] / D;
    const int n_opi  = in_sizes[1] / D;
    const int U      = in_sizes[2] / D;
    const int L      = in_sizes[10] / U;

    __half *pKA, *pB, *pQ;
    cudaGetSymbolAddress((void**)&pKA, g_KA);
    cudaGetSymbolAddress((void**)&pB,  g_B);
    cudaGetSymbolAddress((void**)&pQ,  g_Q);

    const int nbK = (n_item + 255) / 256;
    const int nbA = nbK;
    const int nbB = (n_opi + 255) / 256;
    const int nbQ = (U + 255) / 256;

    const int smemB = 3 * TILE_B;   // 104448 B -> 2 CTAs/SM
    cudaFuncSetAttribute((const void*)tab_gemm_all,
                         cudaFuncAttributeMaxDynamicSharedMemorySize, smemB);

    tab_gemm_all<<<nbK + nbA + nbB + nbQ, 512, smemB>>>(
        item_table, opin_table, user_emb, attr,
        Wq, bq, Wk, bk, Wv, bv,
        pKA, pB, pQ, n_item, n_opi, U, nbK, nbA, nbB);

    const int threads = 256;
    const int blocks  = (U * 32 + threads - 1) / threads;
    attend_kernel<<<blocks, threads>>>(item_seqs, opin_seqs, out, U, L);
}